// round 1
// baseline (speedup 1.0000x reference)
#include <cuda_runtime.h>

#define RANK 53
#define CIN  32
#define COUT 64
#define DIM  56
#define NVOX (56*56*56)   // 175616
#define STRH (56*56)      // 3136
#define STRW 56

// Scratch: two rank-major intermediate tensors [RANK][NVOX] (~35.5 MB each).
__device__ float g_bufA[RANK * NVOX];
__device__ float g_bufB[RANK * NVOX];

// ---------- packed f32x2 helpers (sm_103a) ----------
__device__ __forceinline__ unsigned long long pk2(float lo, float hi) {
    unsigned long long r;
    asm("mov.b64 %0, {%1, %2};" : "=l"(r) : "f"(lo), "f"(hi));
    return r;
}
__device__ __forceinline__ unsigned long long fma2(unsigned long long a,
                                                   unsigned long long b,
                                                   unsigned long long c) {
    unsigned long long d;
    asm("fma.rn.f32x2 %0, %1, %2, %3;" : "=l"(d) : "l"(a), "l"(b), "l"(c));
    return d;
}
__device__ __forceinline__ float2 up2(unsigned long long v) {
    float lo, hi;
    asm("mov.b64 {%0, %1}, %2;" : "=f"(lo), "=f"(hi) : "l"(v));
    return make_float2(lo, hi);
}

// ---------- Kernel 1: pointwise Cin -> RANK  (t0[r,v] = sum_c Ucin[c,r] x[c,v]) ----------
__global__ __launch_bounds__(128)
void k_pointwise(const float* __restrict__ x, const float* __restrict__ Ucin) {
    __shared__ unsigned long long w2[CIN][RANK];   // broadcast-packed weights
    for (int i = threadIdx.x; i < CIN * RANK; i += 128) {
        float v = Ucin[i];
        w2[i / RANK][i % RANK] = pk2(v, v);
    }
    __syncthreads();

    int v = (blockIdx.x * 128 + threadIdx.x) * 4;
    if (v >= NVOX) return;

    unsigned long long xlo[CIN], xhi[CIN];
#pragma unroll
    for (int c = 0; c < CIN; c++) {
        float4 t = *(const float4*)(x + (size_t)c * NVOX + v);
        xlo[c] = pk2(t.x, t.y);
        xhi[c] = pk2(t.z, t.w);
    }

    for (int r = 0; r < RANK; r++) {
        unsigned long long alo = 0ull, ahi = 0ull;   // bits of (0.f,0.f)
#pragma unroll
        for (int c = 0; c < CIN; c++) {
            unsigned long long wv = w2[c][r];
            alo = fma2(wv, xlo[c], alo);
            ahi = fma2(wv, xhi[c], ahi);
        }
        float2 a = up2(alo), b = up2(ahi);
        *(float4*)(g_bufA + (size_t)r * NVOX + v) = make_float4(a.x, a.y, b.x, b.y);
    }
}

// ---------- Kernels 2/3: per-rank 1D 3-tap conv along a strided axis ----------
// out[v] = k0*in[v-STRIDE] + k1*in[v] + k2*in[v+STRIDE], zero-padded at coord 0/55.
template <int STRIDE>
__global__ __launch_bounds__(256)
void k_conv1d(const float* __restrict__ in, float* __restrict__ out,
              const float* __restrict__ Uk) {
    int v = (blockIdx.x * 256 + threadIdx.x) * 4;
    if (v >= RANK * NVOX) return;
    int r     = v / NVOX;
    int rem   = v - r * NVOX;
    int coord = (rem / STRIDE) % DIM;   // same coord for all 4 lanes (STRIDE % 4 == 0)

    float k0 = Uk[r], k1 = Uk[RANK + r], k2 = Uk[2 * RANK + r];
    const float4 z4 = make_float4(0.f, 0.f, 0.f, 0.f);
    float4 c = *(const float4*)(in + v);
    float4 a = (coord > 0)       ? *(const float4*)(in + v - STRIDE) : z4;
    float4 b = (coord < DIM - 1) ? *(const float4*)(in + v + STRIDE) : z4;

    float4 o;
    o.x = k0 * a.x + k1 * c.x + k2 * b.x;
    o.y = k0 * a.y + k1 * c.y + k2 * b.y;
    o.z = k0 * a.z + k1 * c.z + k2 * b.z;
    o.w = k0 * a.w + k1 * c.w + k2 * b.w;
    *(float4*)(out + v) = o;
}

// ---------- Kernel 4: fused depth conv + projection RANK -> COUT + bias ----------
// blockIdx.y in {0,1} selects output-channel half (32 channels per half).
__global__ __launch_bounds__(128)
void k_dproj(const float* __restrict__ in, const float* __restrict__ Ukd,
             const float* __restrict__ Ucout, const float* __restrict__ bias,
             float* __restrict__ out) {
    __shared__ unsigned long long wo2[RANK][32];   // packed Ucout[r, half*32+j]
    __shared__ float kd[3][RANK];
    __shared__ float bsh[32];

    int half = blockIdx.y;
    for (int i = threadIdx.x; i < RANK * 32; i += 128) {
        int r = i >> 5, j = i & 31;
        float v = Ucout[r * COUT + half * 32 + j];
        wo2[r][j] = pk2(v, v);
    }
    for (int i = threadIdx.x; i < 3 * RANK; i += 128)
        kd[i / RANK][i % RANK] = Ukd[i];
    if (threadIdx.x < 32) bsh[threadIdx.x] = bias[half * 32 + threadIdx.x];
    __syncthreads();

    int v = (blockIdx.x * 128 + threadIdx.x) * 4;
    if (v >= NVOX) return;
    int z = v % DIM;   // z of lane 0; lanes cover z..z+3 within one line (DIM%4==0)

    unsigned long long alo[32], ahi[32];
#pragma unroll
    for (int j = 0; j < 32; j++) { alo[j] = 0ull; ahi[j] = 0ull; }

    for (int r = 0; r < RANK; r++) {
        const float* p = in + (size_t)r * NVOX + v;
        float4 c  = *(const float4*)p;
        float  lf = (z > 0)       ? p[-1] : 0.f;
        float  rt = (z + 4 < DIM) ? p[4]  : 0.f;
        float k0 = kd[0][r], k1 = kd[1][r], k2 = kd[2][r];

        float t0 = k0 * lf  + k1 * c.x + k2 * c.y;
        float t1 = k0 * c.x + k1 * c.y + k2 * c.z;
        float t2 = k0 * c.y + k1 * c.z + k2 * c.w;
        float t3 = k0 * c.z + k1 * c.w + k2 * rt;
        unsigned long long tlo = pk2(t0, t1), thi = pk2(t2, t3);

#pragma unroll
        for (int j = 0; j < 32; j++) {
            unsigned long long w = wo2[r][j];
            alo[j] = fma2(w, tlo, alo[j]);
            ahi[j] = fma2(w, thi, ahi[j]);
        }
    }

#pragma unroll
    for (int j = 0; j < 32; j++) {
        int o = half * 32 + j;
        float bb = bsh[j];
        float2 a = up2(alo[j]), b = up2(ahi[j]);
        *(float4*)(out + (size_t)o * NVOX + v) =
            make_float4(a.x + bb, a.y + bb, b.x + bb, b.y + bb);
    }
}

extern "C" void kernel_launch(void* const* d_in, const int* in_sizes, int n_in,
                              void* d_out, int out_size) {
    const float* x     = (const float*)d_in[0];
    const float* Ukh   = (const float*)d_in[1];
    const float* Ukw   = (const float*)d_in[2];
    const float* Ukd   = (const float*)d_in[3];
    const float* Ucin  = (const float*)d_in[4];
    const float* Ucout = (const float*)d_in[5];
    const float* bias  = (const float*)d_in[6];
    float* out = (float*)d_out;

    float *bufA, *bufB;
    cudaGetSymbolAddress((void**)&bufA, g_bufA);
    cudaGetSymbolAddress((void**)&bufB, g_bufB);

    const int vox_blocks = NVOX / (128 * 4);                         // 343 (exact)
    const int conv_blocks = (RANK * NVOX / 4 + 255) / 256;           // 9090

    // 1) pointwise Cin->R into bufA
    k_pointwise<<<vox_blocks, 128>>>(x, Ucin);
    // 2) conv along H: bufA -> bufB
    k_conv1d<STRH><<<conv_blocks, 256>>>(bufA, bufB, Ukh);
    // 3) conv along W: bufB -> bufA
    k_conv1d<STRW><<<conv_blocks, 256>>>(bufB, bufA, Ukw);
    // 4) conv along D + projection + bias: bufA -> out
    dim3 g4(vox_blocks, 2);
    k_dproj<<<g4, 128>>>(bufA, Ukd, Ucout, bias, out);
}

// round 2
// speedup vs baseline: 1.1013x; 1.1013x over previous
#include <cuda_runtime.h>

#define RANK 53
#define CIN  32
#define COUT 64
#define DIM  56
#define NVOX (56*56*56)   // 175616
#define STRH (56*56)      // 3136
#define STRW 56
#define TH 8
#define TW 8

// Scratch: two rank-major intermediates [RANK][NVOX] (~35.5 MB each).
__device__ float g_bufA[RANK * NVOX];
__device__ float g_bufB[RANK * NVOX];

// ---------- packed f32x2 helpers (sm_103a) ----------
__device__ __forceinline__ unsigned long long pk2(float lo, float hi) {
    unsigned long long r;
    asm("mov.b64 %0, {%1, %2};" : "=l"(r) : "f"(lo), "f"(hi));
    return r;
}
__device__ __forceinline__ unsigned long long fma2(unsigned long long a,
                                                   unsigned long long b,
                                                   unsigned long long c) {
    unsigned long long d;
    asm("fma.rn.f32x2 %0, %1, %2, %3;" : "=l"(d) : "l"(a), "l"(b), "l"(c));
    return d;
}
__device__ __forceinline__ float2 up2(unsigned long long v) {
    float lo, hi;
    asm("mov.b64 {%0, %1}, %2;" : "=f"(lo), "=f"(hi) : "l"(v));
    return make_float2(lo, hi);
}

// ---------- Kernel 1: pointwise Cin -> RANK ----------
__global__ __launch_bounds__(128)
void k_pointwise(const float* __restrict__ x, const float* __restrict__ Ucin) {
    __shared__ unsigned long long w2[CIN][RANK];
    for (int i = threadIdx.x; i < CIN * RANK; i += 128) {
        float v = Ucin[i];
        w2[i / RANK][i % RANK] = pk2(v, v);
    }
    __syncthreads();

    int v = (blockIdx.x * 128 + threadIdx.x) * 4;
    if (v >= NVOX) return;

    unsigned long long xlo[CIN], xhi[CIN];
#pragma unroll
    for (int c = 0; c < CIN; c++) {
        float4 t = *(const float4*)(x + (size_t)c * NVOX + v);
        xlo[c] = pk2(t.x, t.y);
        xhi[c] = pk2(t.z, t.w);
    }

    for (int r = 0; r < RANK; r++) {
        unsigned long long alo = 0ull, ahi = 0ull;
#pragma unroll
        for (int c = 0; c < CIN; c++) {
            unsigned long long wv = w2[c][r];
            alo = fma2(wv, xlo[c], alo);
            ahi = fma2(wv, xhi[c], ahi);
        }
        float2 a = up2(alo), b = up2(ahi);
        *(float4*)(g_bufA + (size_t)r * NVOX + v) = make_float4(a.x, a.y, b.x, b.y);
    }
}

// ---------- Kernel 2: fused H+W 3-tap separable conv, smem tiled ----------
// out(h,w,d) = sum_{i,j} kh[i]*kw[j] * in(h-1+i, w-1+j, d), zero-padded.
__global__ __launch_bounds__(128)
void k_convHW(const float* __restrict__ in, float* __restrict__ out,
              const float* __restrict__ Ukh, const float* __restrict__ Ukw) {
    __shared__ float s[(TH + 2) * (TW + 2) * DIM];   // 22.4 KB

    int r  = blockIdx.z;
    int h0 = blockIdx.y * TH;
    int w0 = blockIdx.x * TW;
    const float* base = in + (size_t)r * NVOX;

    // load (TH+2)x(TW+2)x56 tile with zero padding, float4 granules
    const int NLOAD4 = (TH + 2) * (TW + 2) * (DIM / 4);   // 1400
    for (int i = threadIdx.x; i < NLOAD4; i += 128) {
        int dq = i % (DIM / 4);
        int t  = i / (DIM / 4);
        int lw = t % (TW + 2);
        int lh = t / (TW + 2);
        int gh = h0 + lh - 1, gw = w0 + lw - 1;
        float4 val = make_float4(0.f, 0.f, 0.f, 0.f);
        if (gh >= 0 && gh < DIM && gw >= 0 && gw < DIM)
            val = *(const float4*)(base + gh * STRH + gw * STRW + dq * 4);
        *(float4*)(s + (lh * (TW + 2) + lw) * DIM + dq * 4) = val;
    }
    __syncthreads();

    float kh[3] = {Ukh[r], Ukh[RANK + r], Ukh[2 * RANK + r]};
    float kw[3] = {Ukw[r], Ukw[RANK + r], Ukw[2 * RANK + r]};
    float kk[9];
#pragma unroll
    for (int i = 0; i < 3; i++)
#pragma unroll
        for (int j = 0; j < 3; j++) kk[i * 3 + j] = kh[i] * kw[j];

    float* obase = out + (size_t)r * NVOX;
    const int NOUT4 = TH * TW * (DIM / 4);   // 896 -> 7 per thread
    for (int o = threadIdx.x; o < NOUT4; o += 128) {
        int dq = o % (DIM / 4);
        int t  = o / (DIM / 4);
        int lw = t % TW;
        int lh = t / TW;
        float4 acc = make_float4(0.f, 0.f, 0.f, 0.f);
#pragma unroll
        for (int i = 0; i < 3; i++)
#pragma unroll
            for (int j = 0; j < 3; j++) {
                const float4 v = *(const float4*)(s + ((lh + i) * (TW + 2) + (lw + j)) * DIM + dq * 4);
                float c = kk[i * 3 + j];
                acc.x += c * v.x; acc.y += c * v.y;
                acc.z += c * v.z; acc.w += c * v.w;
            }
        *(float4*)(obase + (h0 + lh) * STRH + (w0 + lw) * STRW + dq * 4) = acc;
    }
}

// ---------- Kernel 3: fused depth conv + projection RANK -> 16 ch + bias ----------
// blockIdx.y in {0..3} selects a 16-channel quarter.
__global__ __launch_bounds__(128)
void k_dproj(const float* __restrict__ in, const float* __restrict__ Ukd,
             const float* __restrict__ Ucout, const float* __restrict__ bias,
             float* __restrict__ out) {
    __shared__ unsigned long long wo2[RANK][16];
    __shared__ float kd[3][RANK];
    __shared__ float bsh[16];

    int quart = blockIdx.y;
    for (int i = threadIdx.x; i < RANK * 16; i += 128) {
        int r = i >> 4, j = i & 15;
        float v = Ucout[r * COUT + quart * 16 + j];
        wo2[r][j] = pk2(v, v);
    }
    for (int i = threadIdx.x; i < 3 * RANK; i += 128)
        kd[i / RANK][i % RANK] = Ukd[i];
    if (threadIdx.x < 16) bsh[threadIdx.x] = bias[quart * 16 + threadIdx.x];
    __syncthreads();

    int v = (blockIdx.x * 128 + threadIdx.x) * 4;
    if (v >= NVOX) return;
    int z = v % DIM;

    unsigned long long alo[16], ahi[16];
#pragma unroll
    for (int j = 0; j < 16; j++) { alo[j] = 0ull; ahi[j] = 0ull; }

    for (int r = 0; r < RANK; r++) {
        const float* p = in + (size_t)r * NVOX + v;
        float4 c  = *(const float4*)p;
        float  lf = (z > 0)       ? p[-1] : 0.f;
        float  rt = (z + 4 < DIM) ? p[4]  : 0.f;
        float k0 = kd[0][r], k1 = kd[1][r], k2 = kd[2][r];

        float t0 = k0 * lf  + k1 * c.x + k2 * c.y;
        float t1 = k0 * c.x + k1 * c.y + k2 * c.z;
        float t2 = k0 * c.y + k1 * c.z + k2 * c.w;
        float t3 = k0 * c.z + k1 * c.w + k2 * rt;
        unsigned long long tlo = pk2(t0, t1), thi = pk2(t2, t3);

#pragma unroll
        for (int j = 0; j < 16; j++) {
            unsigned long long w = wo2[r][j];
            alo[j] = fma2(w, tlo, alo[j]);
            ahi[j] = fma2(w, thi, ahi[j]);
        }
    }

#pragma unroll
    for (int j = 0; j < 16; j++) {
        int o = quart * 16 + j;
        float bb = bsh[j];
        float2 a = up2(alo[j]), b = up2(ahi[j]);
        *(float4*)(out + (size_t)o * NVOX + v) =
            make_float4(a.x + bb, a.y + bb, b.x + bb, b.y + bb);
    }
}

extern "C" void kernel_launch(void* const* d_in, const int* in_sizes, int n_in,
                              void* d_out, int out_size) {
    const float* x     = (const float*)d_in[0];
    const float* Ukh   = (const float*)d_in[1];
    const float* Ukw   = (const float*)d_in[2];
    const float* Ukd   = (const float*)d_in[3];
    const float* Ucin  = (const float*)d_in[4];
    const float* Ucout = (const float*)d_in[5];
    const float* bias  = (const float*)d_in[6];
    float* out = (float*)d_out;

    float *bufA, *bufB;
    cudaGetSymbolAddress((void**)&bufA, g_bufA);
    cudaGetSymbolAddress((void**)&bufB, g_bufB);

    const int vox_blocks = NVOX / (128 * 4);   // 343 exact

    // 1) pointwise Cin->R into bufA
    k_pointwise<<<vox_blocks, 128>>>(x, Ucin);
    // 2) fused conv along H and W: bufA -> bufB
    dim3 g2(DIM / TW, DIM / TH, RANK);         // 7 x 7 x 53
    k_convHW<<<g2, 128>>>(bufA, bufB, Ukh, Ukw);
    // 3) conv along D + projection + bias: bufB -> out
    dim3 g3(vox_blocks, 4);
    k_dproj<<<g3, 128>>>(bufB, Ukd, Ucout, bias, out);
}